// round 7
// baseline (speedup 1.0000x reference)
#include <cuda_runtime.h>
#include <math.h>

typedef unsigned long long ull;

// ---------------- problem constants ----------------
#define Bb   4
#define Cc   64
#define Hh   5
#define Ww   5
#define Kk   3
#define Ee   12
#define NHh  4
#define DHh  3
#define FFf  24
#define HOo  3
#define WOo  3
#define Ll   9
#define Ss   (Bb*Cc*Kk*Kk)       // 2304
#define ROWS (Ss*Ll)             // 20736
#define NC   (Ll*NHh)            // 36
#define YSZ  (Bb*Cc*Hh*Ww)       // 6400

// attention tiling
#define QPB   96                 // threads per attn block (3 warps)
#define QPT   8                  // queries per thread (4 packed pairs)
#define NQC   3                  // query chunks  (2304 / (96*8))
#define NTC   8                  // t-splits
#define TCH   (Ss/NTC)           // 288 t per block

// ---------------- scratch ----------------
__device__ float      g_seq[ROWS*Ee];          // l-major rows: row = l*Ss + s
__device__ float      g_q[NC*Ss*DHh];          // scaled by log2(e)/sqrt(3)
__device__ ulonglong2 g_kvd[NC*Ss*3];          // dup-packed: {kx,kx,ky,ky},{kz,kz,vx,vx},{vy,vy,vz,vz}
__device__ float4     g_part[NTC*NC*Ss];       // [tc][combo][s] -> {sum, a0, a1, a2}

// ---------------- packed f32x2 helpers ----------------
__device__ __forceinline__ ull ffma2(ull a, ull b, ull c) {
    ull d; asm("fma.rn.f32x2 %0, %1, %2, %3;" : "=l"(d) : "l"(a), "l"(b), "l"(c)); return d;
}
__device__ __forceinline__ ull fmul2(ull a, ull b) {
    ull d; asm("mul.rn.f32x2 %0, %1, %2;" : "=l"(d) : "l"(a), "l"(b)); return d;
}
__device__ __forceinline__ ull fadd2(ull a, ull b) {
    ull d; asm("add.rn.f32x2 %0, %1, %2;" : "=l"(d) : "l"(a), "l"(b)); return d;
}
__device__ __forceinline__ ull pack2(float lo, float hi) {
    ull d; asm("mov.b64 %0, {%1, %2};" : "=l"(d) : "f"(lo), "f"(hi)); return d;
}
__device__ __forceinline__ void unpack2(ull v, float& lo, float& hi) {
    asm("mov.b64 {%0, %1}, %2;" : "=f"(lo), "=f"(hi) : "l"(v));
}
__device__ __forceinline__ ull ex2pair(ull s) {
    ull r;
    asm("{\n\t"
        ".reg .f32 lo, hi;\n\t"
        "mov.b64 {lo, hi}, %1;\n\t"
        "ex2.approx.f32 lo, lo;\n\t"
        "ex2.approx.f32 hi, hi;\n\t"
        "mov.b64 %0, {lo, hi};\n\t"
        "}" : "=l"(r) : "l"(s));
    return r;
}

// ---------------- kernel 1: unfold + embeddings + QKV projection ----------------
// thread per (row, head); role = blockIdx.y + role0 (0=q, 1=k, 2=v)
__global__ void k_embed_qkv(const float* __restrict__ x,
                            const float* __restrict__ ce,
                            const float* __restrict__ pe,
                            const float* __restrict__ wqkv,
                            const float* __restrict__ bqkv,
                            float* __restrict__ y,
                            int role0)
{
    int role = blockIdx.y + role0;
    __shared__ float sw[Ee*Ee];
    __shared__ float sb[Ee];
    for (int i = threadIdx.x; i < Ee*Ee; i += blockDim.x) sw[i] = wqkv[role*Ee*Ee + i];
    if (threadIdx.x < Ee) sb[threadIdx.x] = bqkv[role*Ee + threadIdx.x];
    __syncthreads();

    int gt  = blockIdx.x*blockDim.x + threadIdx.x;
    int row = gt >> 2;            // l-major: row = l*Ss + s
    int h   = gt & 3;
    if (row >= ROWS) return;
    int l = row / Ss, s = row % Ss;
    int b   = s / (Cc*Kk*Kk);
    int rem = s % (Cc*Kk*Kk);
    int c = rem / (Kk*Kk), p = rem % (Kk*Kk);
    int i = p / Kk, j = p % Kk;
    int oi = l / WOo, oj = l % WOo;

    float xv = x[((b*Cc + c)*Hh + (i+oi))*Ww + (j+oj)];

    float r[Ee];
    #pragma unroll
    for (int e = 0; e < Ee; e++) r[e] = ce[c*Ee + e] + pe[l*Ee + e] + xv;

    if (role == 0) {
        #pragma unroll
        for (int d = 0; d < DHh; d++) g_seq[row*Ee + h*DHh + d] = r[h*DHh + d];
        if (h == 0 && row < YSZ) y[row] = 0.f;    // zero output for atomics
    }

    float out[DHh];
    #pragma unroll
    for (int d = 0; d < DHh; d++) {
        int e = h*DHh + d;
        float acc = sb[e];
        #pragma unroll
        for (int f = 0; f < Ee; f++) acc += r[f] * sw[e*Ee + f];
        out[d] = acc;
    }

    float4* kvd = (float4*)g_kvd;
    int idx = ((l*NHh + h)*Ss + s)*3;
    if (role == 0) {
        const float qscale = 0.57735026918962576f * 1.4426950408889634f; // 1/sqrt(3)*log2(e)
        int base = ((l*NHh + h)*Ss + s)*DHh;
        g_q[base+0] = out[0]*qscale;
        g_q[base+1] = out[1]*qscale;
        g_q[base+2] = out[2]*qscale;
    } else if (role == 1) {
        kvd[idx] = make_float4(out[0], out[0], out[1], out[1]);
        reinterpret_cast<float2*>(kvd + idx + 1)[0] = make_float2(out[2], out[2]);
    } else {
        reinterpret_cast<float2*>(kvd + idx + 1)[1] = make_float2(out[0], out[0]);
        kvd[idx+2] = make_float4(out[1], out[1], out[2], out[2]);
    }
}

// ---------------- kernel 2: attention partials ----------------
// grid (36 combos, 3 q-chunks, 8 t-chunks), 96 threads, 8 queries/thread (4 packed pairs).
__global__ void k_attn()
{
    __shared__ ulonglong2 kvs[TCH*3];   // 13.8 KB

    int combo = blockIdx.x;
    int tid   = threadIdx.x;
    int s0 = blockIdx.y*(QPB*QPT) + tid;       // queries s0 + 96*j, j=0..7
    int tb = blockIdx.z*TCH;

    // stage K/V chunk (pre-duplicated pairs)
    {
        const ulonglong2* src = g_kvd + (combo*Ss + tb)*3;
        for (int i = tid; i < TCH*3; i += QPB) kvs[i] = src[i];
    }

    // load 8 queries, pack as 4 pairs
    const float* qg = g_q + (combo*Ss + s0)*DHh;
    ull px[4], py[4], pz[4];
    #pragma unroll
    for (int pq = 0; pq < 4; pq++) {
        const float* qa = qg + (2*pq  )*QPB*DHh;
        const float* qb = qg + (2*pq+1)*QPB*DHh;
        px[pq] = pack2(qa[0], qb[0]);
        py[pq] = pack2(qa[1], qb[1]);
        pz[pq] = pack2(qa[2], qb[2]);
    }

    ull sum[4] = {0,0,0,0};
    ull a0[4]  = {0,0,0,0};
    ull a1[4]  = {0,0,0,0};
    ull a2[4]  = {0,0,0,0};

    __syncthreads();

    #pragma unroll 4
    for (int t = 0; t < TCH; t++) {
        ulonglong2 u0 = kvs[3*t];     // {kx2, ky2}
        ulonglong2 u1 = kvs[3*t+1];   // {kz2, vx2}
        ulonglong2 u2 = kvs[3*t+2];   // {vy2, vz2}

        #pragma unroll
        for (int pq = 0; pq < 4; pq++) {
            ull sc = ffma2(px[pq], u0.x, ffma2(py[pq], u0.y, fmul2(pz[pq], u1.x)));
            ull w  = ex2pair(sc);
            sum[pq] = fadd2(sum[pq], w);
            a0[pq]  = ffma2(w, u1.y, a0[pq]);
            a1[pq]  = ffma2(w, u2.x, a1[pq]);
            a2[pq]  = ffma2(w, u2.y, a2[pq]);
        }
    }

    int tc = blockIdx.z;
    #pragma unroll
    for (int pq = 0; pq < 4; pq++) {
        float sA, sB, x0A, x0B, x1A, x1B, x2A, x2B;
        unpack2(sum[pq], sA, sB);
        unpack2(a0[pq], x0A, x0B);
        unpack2(a1[pq], x1A, x1B);
        unpack2(a2[pq], x2A, x2B);
        int sa = s0 + (2*pq)*QPB;
        g_part[(tc*NC + combo)*Ss + sa      ] = make_float4(sA, x0A, x1A, x2A);
        g_part[(tc*NC + combo)*Ss + sa + QPB] = make_float4(sB, x0B, x1B, x2B);
    }
}

// ---------------- kernel 3: combine + out_proj + LN1 + FFN + LN2 + linear + fold ----------------
// TWO threads per row (lane pair). half = tid&1 splits features 6/6, tc 4/4, heads' partials via shfl.
__global__ void k_post(const float* __restrict__ wo, const float* __restrict__ bo,
                       const float* __restrict__ g1, const float* __restrict__ b1,
                       const float* __restrict__ f1w, const float* __restrict__ f1b,
                       const float* __restrict__ f2w, const float* __restrict__ f2b,
                       const float* __restrict__ g2, const float* __restrict__ b2,
                       const float* __restrict__ lw, const float* __restrict__ lb,
                       float* __restrict__ y)
{
    __shared__ float swo[Ee*Ee], sbo[Ee], sg1[Ee], sb1[Ee];
    __shared__ float s1[FFf*Ee], s1b[FFf], s2[Ee*FFf], s2b[Ee];
    __shared__ float sg2[Ee], sb2[Ee], slw[Ee], slb;
    for (int i = threadIdx.x; i < Ee*Ee; i += blockDim.x) swo[i] = wo[i];
    for (int i = threadIdx.x; i < FFf*Ee; i += blockDim.x) { s1[i] = f1w[i]; s2[i] = f2w[i]; }
    if (threadIdx.x < FFf) s1b[threadIdx.x] = f1b[threadIdx.x];
    if (threadIdx.x < Ee) {
        sbo[threadIdx.x] = bo[threadIdx.x];
        sg1[threadIdx.x] = g1[threadIdx.x];
        sb1[threadIdx.x] = b1[threadIdx.x];
        s2b[threadIdx.x] = f2b[threadIdx.x];
        sg2[threadIdx.x] = g2[threadIdx.x];
        sb2[threadIdx.x] = b2[threadIdx.x];
        slw[threadIdx.x] = lw[threadIdx.x];
    }
    if (threadIdx.x == 0) slb = lb[0];
    __syncthreads();

    int gt   = blockIdx.x*blockDim.x + threadIdx.x;
    int row  = gt >> 1;                  // l-major: row = l*Ss + s
    int half = gt & 1;
    int l = row / Ss, s = row % Ss;
    const unsigned FULL = 0xFFFFFFFFu;

    // ---- combine attention partials (tc split 4/4, shfl-reduced) ----
    float cx[Ee];
    #pragma unroll
    for (int h = 0; h < NHh; h++) {
        int combo = l*NHh + h;
        float4 acc = make_float4(0.f, 0.f, 0.f, 0.f);
        #pragma unroll
        for (int tcl = 0; tcl < NTC/2; tcl++) {
            int tc = half*(NTC/2) + tcl;
            float4 q = g_part[(tc*NC + combo)*Ss + s];
            acc.x += q.x; acc.y += q.y; acc.z += q.z; acc.w += q.w;
        }
        acc.x += __shfl_xor_sync(FULL, acc.x, 1);
        acc.y += __shfl_xor_sync(FULL, acc.y, 1);
        acc.z += __shfl_xor_sync(FULL, acc.z, 1);
        acc.w += __shfl_xor_sync(FULL, acc.w, 1);
        float inv = 1.f / acc.x;
        cx[h*3]   = acc.y * inv;
        cx[h*3+1] = acc.z * inv;
        cx[h*3+2] = acc.w * inv;
    }

    int ebase = half*6;

    // ---- out_proj + residual (own 6 outputs) ----
    float t[6];
    #pragma unroll
    for (int eo = 0; eo < 6; eo++) {
        int e = ebase + eo;
        float acc = sbo[e];
        #pragma unroll
        for (int f = 0; f < Ee; f++) acc += cx[f] * swo[e*Ee + f];
        t[eo] = g_seq[row*Ee + e] + acc;
    }

    // ---- LN1 (pair reduction) ----
    float sl = 0.f;
    #pragma unroll
    for (int eo = 0; eo < 6; eo++) sl += t[eo];
    float mu = (sl + __shfl_xor_sync(FULL, sl, 1)) * (1.f/Ee);
    float vl = 0.f;
    #pragma unroll
    for (int eo = 0; eo < 6; eo++) { float d = t[eo]-mu; vl += d*d; }
    float var = (vl + __shfl_xor_sync(FULL, vl, 1)) * (1.f/Ee);
    float rs = rsqrtf(var + 1e-5f);

    float h1[6];
    #pragma unroll
    for (int eo = 0; eo < 6; eo++) {
        int e = ebase + eo;
        h1[eo] = (t[eo]-mu)*rs*sg1[e] + sb1[e];
    }

    // ---- FF1: each thread partial-dots its 6 features for ALL 24 hidden ----
    float hid[FFf];
    #pragma unroll
    for (int f = 0; f < FFf; f++) {
        float p = 0.f;
        #pragma unroll
        for (int eo = 0; eo < 6; eo++) p += h1[eo] * s1[f*Ee + ebase + eo];
        p += __shfl_xor_sync(FULL, p, 1);
        hid[f] = fmaxf(p + s1b[f], 0.f);
    }

    // ---- FF2 + residual (own 6 outputs, full hidden available) ----
    float t2[6];
    #pragma unroll
    for (int eo = 0; eo < 6; eo++) {
        int e = ebase + eo;
        float acc = s2b[e];
        #pragma unroll
        for (int f = 0; f < FFf; f++) acc += hid[f] * s2[e*FFf + f];
        t2[eo] = h1[eo] + acc;
    }

    // ---- LN2 (pair reduction) ----
    float sl2 = 0.f;
    #pragma unroll
    for (int eo = 0; eo < 6; eo++) sl2 += t2[eo];
    float mu2 = (sl2 + __shfl_xor_sync(FULL, sl2, 1)) * (1.f/Ee);
    float vl2 = 0.f;
    #pragma unroll
    for (int eo = 0; eo < 6; eo++) { float d = t2[eo]-mu2; vl2 += d*d; }
    float var2 = (vl2 + __shfl_xor_sync(FULL, vl2, 1)) * (1.f/Ee);
    float rs2 = rsqrtf(var2 + 1e-5f);

    // ---- final linear (pair-reduced dot) ----
    float pl = 0.f;
    #pragma unroll
    for (int eo = 0; eo < 6; eo++) {
        int e = ebase + eo;
        pl += ((t2[eo]-mu2)*rs2*sg2[e] + sb2[e]) * slw[e];
    }
    pl += __shfl_xor_sync(FULL, pl, 1);

    if (half == 0) {
        float proj = slb + pl;
        int b   = s / (Cc*Kk*Kk);
        int rem = s % (Cc*Kk*Kk);
        int c = rem / (Kk*Kk), p = rem % (Kk*Kk);
        int i = p / Kk, j = p % Kk;
        int oi = l / WOo, oj = l % WOo;
        atomicAdd(&y[((b*Cc + c)*Hh + (i+oi))*Ww + (j+oj)], proj);
    }
}

// ---------------- launch ----------------
extern "C" void kernel_launch(void* const* d_in, const int* in_sizes, int n_in,
                              void* d_out, int out_size)
{
    const float* x    = (const float*)d_in[0];
    const float* ce   = (const float*)d_in[1];
    const float* pe   = (const float*)d_in[2];
    const float* ipw  = (const float*)d_in[3];
    const float* ipb  = (const float*)d_in[4];
    const float* opw  = (const float*)d_in[5];
    const float* opb  = (const float*)d_in[6];
    const float* ln1w = (const float*)d_in[7];
    const float* ln1b = (const float*)d_in[8];
    const float* f1w  = (const float*)d_in[9];
    const float* f1b  = (const float*)d_in[10];
    const float* f2w  = (const float*)d_in[11];
    const float* f2b  = (const float*)d_in[12];
    const float* ln2w = (const float*)d_in[13];
    const float* ln2b = (const float*)d_in[14];
    const float* lw   = (const float*)d_in[15];
    const float* lb   = (const float*)d_in[16];
    float* y = (float*)d_out;

    dim3 eg1(ROWS*NHh/128, 1);   // role 0 (q) — also writes g_seq, zeroes y
    dim3 eg2(ROWS*NHh/128, 2);   // roles 1,2 (k, v)
    k_embed_qkv<<<eg1, 128>>>(x, ce, pe, ipw, ipb, y, 0);
    k_embed_qkv<<<eg2, 128>>>(x, ce, pe, ipw, ipb, y, 1);
    dim3 agrid(NC, NQC, NTC);
    k_attn<<<agrid, QPB>>>();
    k_post<<<ROWS*2/128, 128>>>(opw, opb, ln1w, ln1b, f1w, f1b, f2w, f2b, ln2w, ln2b, lw, lb, y);
}

// round 8
// speedup vs baseline: 2.8521x; 2.8521x over previous
#include <cuda_runtime.h>
#include <math.h>

typedef unsigned long long ull;

// ---------------- problem constants ----------------
#define Bb   4
#define Cc   64
#define Hh   5
#define Ww   5
#define Kk   3
#define Ee   12
#define NHh  4
#define DHh  3
#define FFf  24
#define HOo  3
#define WOo  3
#define Ll   9
#define Ss   (Bb*Cc*Kk*Kk)       // 2304
#define ROWS (Ss*Ll)             // 20736
#define NC   (Ll*NHh)            // 36
#define YSZ  (Bb*Cc*Hh*Ww)       // 6400

#define DEG  16                  // Taylor degree: pairs j=0..16, moments M_0..M_17

// ---------------- scratch ----------------
__device__ float  TMg[Ll*Cc*36];        // per (l,c'): pairs {M_j/j!, M_{j+1}/j!} j=0..16, padded to 36 floats (144B)
__device__ float4 TAg[NC*Cc];           // per (combo,c): {a0,a1,a2, gamma}   (a scaled 1/sqrt3)
__device__ float4 TBg[NC*Cc*2];         // per (combo,c'): {b0,b1,b2,0}*log2e , {v00,v01,v02,0}
__device__ float4 TWg[NC];              // per combo: {delta, wv0, wv1, wv2}
__device__ float4 TUg[NHh];             // per head:  {u0,u1,u2,0}  (scaled 1/sqrt3)
__device__ float4 g_ctx[NC*Ss];         // attention output per (combo, s): {c0,c1,c2,0}

// ---------------- packed f32x2 helpers ----------------
__device__ __forceinline__ ull ffma2(ull a, ull b, ull c) {
    ull d; asm("fma.rn.f32x2 %0, %1, %2, %3;" : "=l"(d) : "l"(a), "l"(b), "l"(c)); return d;
}
__device__ __forceinline__ ull pack2(float lo, float hi) {
    ull d; asm("mov.b64 %0, {%1, %2};" : "=l"(d) : "f"(lo), "f"(hi)); return d;
}
__device__ __forceinline__ void unpack2(ull v, float& lo, float& hi) {
    asm("mov.b64 {%0, %1}, %2;" : "=f"(lo), "=f"(hi) : "l"(v));
}
__device__ __forceinline__ float ex2(float x) {
    float r; asm("ex2.approx.f32 %0, %1;" : "=f"(r) : "f"(x)); return r;
}

// ---------------- kernel 0: channel moments (fp64) + zero y ----------------
// thread per (l, c'): 36 x-samples, accumulate M_0..M_17 in double, store premultiplied pairs.
__global__ void k_moments(const float* __restrict__ x, float* __restrict__ y)
{
    int gid = blockIdx.x*blockDim.x + threadIdx.x;
    for (int i = gid; i < YSZ; i += 640) y[i] = 0.f;
    if (gid >= Ll*Cc) return;
    int l = gid / Cc, c = gid % Cc;
    int oi = l / WOo, oj = l % WOo;

    double m[18];
    #pragma unroll
    for (int k = 0; k < 18; k++) m[k] = 0.0;

    for (int b = 0; b < Bb; b++) {
        #pragma unroll
        for (int p = 0; p < 9; p++) {
            int pi = p/3, pj = p%3;
            double xv = (double)x[((b*Cc + c)*Hh + pi + oi)*Ww + pj + oj];
            double x2 = xv*xv, x3 = x2*xv, x4 = x2*x2;
            double x5 = x4*xv, x6 = x4*x2, x7 = x4*x3, x8 = x4*x4;
            double pw[18];
            pw[0]=1.0;   pw[1]=xv;     pw[2]=x2;     pw[3]=x3;
            pw[4]=x4;    pw[5]=x5;     pw[6]=x6;     pw[7]=x7;
            pw[8]=x8;    pw[9]=x8*xv;  pw[10]=x8*x2; pw[11]=x8*x3;
            pw[12]=x8*x4; pw[13]=x8*x5; pw[14]=x8*x6; pw[15]=x8*x7;
            pw[16]=x8*x8; pw[17]=x8*x8*xv;
            #pragma unroll
            for (int k = 0; k < 18; k++) m[k] += pw[k];
        }
    }

    float* dst = TMg + (l*Cc + c)*36;
    double invf = 1.0;
    #pragma unroll
    for (int j = 0; j <= DEG; j++) {
        if (j > 0) invf /= (double)j;      // invf = 1/j!
        dst[2*j]   = (float)(m[j]   * invf);
        dst[2*j+1] = (float)(m[j+1] * invf);
    }
    dst[34] = 0.f; dst[35] = 0.f;
}

// ---------------- kernel 1: per-combo affine tables ----------------
// thread per (combo, c): 2304 threads.
__global__ void k_tables(const float* __restrict__ ce,
                         const float* __restrict__ pe,
                         const float* __restrict__ ipw,
                         const float* __restrict__ ipb)
{
    int gid = blockIdx.x*blockDim.x + threadIdx.x;
    if (gid >= NC*Cc) return;
    int combo = gid >> 6, c = gid & 63;
    int l = combo >> 2, h = combo & 3;

    const float IS3 = 0.57735026918962576f;   // 1/sqrt(3)
    const float L2E = 1.4426950408889634f;

    float rc[Ee];
    #pragma unroll
    for (int f = 0; f < Ee; f++) rc[f] = ce[c*Ee + f] + pe[l*Ee + f];

    float a[3], b[3], v0[3], u[3], w[3], wv[3];
    #pragma unroll
    for (int d = 0; d < 3; d++) {
        const float* Wq = ipw + (3*h + d)*Ee;
        const float* Wk = ipw + (Ee + 3*h + d)*Ee;
        const float* Wv = ipw + (2*Ee + 3*h + d)*Ee;
        float aq = ipb[3*h + d];
        float ak = ipb[Ee + 3*h + d];
        float av = ipb[2*Ee + 3*h + d];
        float uq = 0.f, uk = 0.f, uv = 0.f;
        #pragma unroll
        for (int f = 0; f < Ee; f++) {
            float wq = Wq[f], wk = Wk[f], wvv = Wv[f];
            aq += wq*rc[f]; ak += wk*rc[f]; av += wvv*rc[f];
            uq += wq; uk += wk; uv += wvv;
        }
        a[d] = aq*IS3; b[d] = ak; v0[d] = av;
        u[d] = uq*IS3; w[d] = uk; wv[d] = uv;
    }
    float gamma = a[0]*w[0] + a[1]*w[1] + a[2]*w[2];
    float delta = u[0]*w[0] + u[1]*w[1] + u[2]*w[2];

    TAg[combo*Cc + c] = make_float4(a[0], a[1], a[2], gamma);
    TBg[(combo*Cc + c)*2 + 0] = make_float4(b[0]*L2E, b[1]*L2E, b[2]*L2E, 0.f);
    TBg[(combo*Cc + c)*2 + 1] = make_float4(v0[0], v0[1], v0[2], 0.f);
    if (c == 0) TWg[combo] = make_float4(delta, wv[0], wv[1], wv[2]);
    if (c == 0 && l == 0) TUg[h] = make_float4(u[0], u[1], u[2], 0.f);
}

// ---------------- kernel 2: attention via channel moments ----------------
// grid (36 combos, 18 q-chunks), 128 threads, 1 query/thread.
// weight(s,t) = exp(q~·b_c' + g·x_t), g = q~·w. Inner sums over each channel's
// 36 tokens collapse to Taylor dots against moments: S0=Σe^{gx}, S1=Σx e^{gx}.
__global__ void k_attn()
{
    __shared__ float4 sTB[Cc*2];            // {b~, v0} per c'
    __shared__ ulonglong2 sTM[Cc*9];        // 17 coeff pairs + pad per c'

    int combo = blockIdx.x;
    int l = combo >> 2, h = combo & 3;
    int tid = threadIdx.x;

    for (int i = tid; i < Cc*2; i += 128) sTB[i] = TBg[combo*Cc*2 + i];
    const ulonglong2* tms = (const ulonglong2*)(TMg + l*Cc*36);
    for (int i = tid; i < Cc*9; i += 128) sTM[i] = tms[i];
    __syncthreads();

    int s = blockIdx.y*128 + tid;
    int bi = s / (Cc*9);
    int rem = s % (Cc*9);
    int c = rem / 9, p = rem % 9;
    int pi = p/3, pj = p%3;
    int oi = l/WOo, oj = l%WOo;
    // x_s : query pixel (read via __ldg; broadcast-ish within block)
    extern __shared__ int _dummy[];
    const float* xg = (const float*)0;      // placeholder (x passed via TXg below)
    (void)xg; (void)_dummy;

    // x pointer comes in through constant table? -> pass as kernel arg instead
    // (see launch: k_attn takes x)
    return; // overwritten by real implementation below
}

// real attention kernel (takes x as argument)
__global__ void k_attn2(const float* __restrict__ x)
{
    __shared__ float4 sTB[Cc*2];
    __shared__ ulonglong2 sTM[Cc*9];

    int combo = blockIdx.x;
    int l = combo >> 2, h = combo & 3;
    int tid = threadIdx.x;

    for (int i = tid; i < Cc*2; i += 128) sTB[i] = TBg[combo*Cc*2 + i];
    const ulonglong2* tms = (const ulonglong2*)(TMg + l*Cc*36);
    for (int i = tid; i < Cc*9; i += 128) sTM[i] = tms[i];
    __syncthreads();

    int s = blockIdx.y*128 + tid;
    int bi = s / (Cc*9);
    int rem = s % (Cc*9);
    int c = rem / 9, p = rem % 9;
    int pi = p/3, pj = p%3;
    int oi = l/WOo, oj = l%WOo;
    float xv = x[((bi*Cc + c)*Hh + pi + oi)*Ww + pj + oj];

    float4 ag = TAg[combo*Cc + c];
    float4 uu = TUg[h];
    float4 dw = TWg[combo];

    float q0 = ag.x + xv*uu.x;
    float q1 = ag.y + xv*uu.y;
    float q2 = ag.z + xv*uu.z;
    float g  = ag.w + xv*dw.x;              // q~·w
    ull  g2  = pack2(g, g);

    float den = 0.f, o0 = 0.f, o1 = 0.f, o2 = 0.f;

    #pragma unroll 2
    for (int cp = 0; cp < Cc; cp++) {
        float4 bb = sTB[cp*2];
        float4 vv = sTB[cp*2 + 1];
        const ull* Cp = (const ull*)&sTM[cp*9];

        float earg = fmaf(q0, bb.x, fmaf(q1, bb.y, q2*bb.z));   // already *log2e
        float E = ex2(earg);

        ull acc = Cp[DEG];
        #pragma unroll
        for (int j = DEG-1; j >= 0; j--) acc = ffma2(acc, g2, Cp[j]);
        float S0, S1; unpack2(acc, S0, S1);

        float ES0 = E*S0, ES1 = E*S1;
        den += ES0;
        o0 = fmaf(ES1, dw.y, fmaf(ES0, vv.x, o0));
        o1 = fmaf(ES1, dw.z, fmaf(ES0, vv.y, o1));
        o2 = fmaf(ES1, dw.w, fmaf(ES0, vv.z, o2));
    }

    float inv = 1.f / den;
    g_ctx[combo*Ss + s] = make_float4(o0*inv, o1*inv, o2*inv, 0.f);
}

// ---------------- kernel 3: out_proj + LN1 + FFN + LN2 + linear + fold ----------------
__global__ void k_post(const float* __restrict__ x,
                       const float* __restrict__ cemb, const float* __restrict__ pemb,
                       const float* __restrict__ wo, const float* __restrict__ bo,
                       const float* __restrict__ g1, const float* __restrict__ b1,
                       const float* __restrict__ f1w, const float* __restrict__ f1b,
                       const float* __restrict__ f2w, const float* __restrict__ f2b,
                       const float* __restrict__ g2, const float* __restrict__ b2,
                       const float* __restrict__ lw, const float* __restrict__ lb,
                       float* __restrict__ y)
{
    __shared__ float swo[Ee*Ee], sbo[Ee], sg1[Ee], sb1[Ee];
    __shared__ float s1[FFf*Ee], s1b[FFf], s2[Ee*FFf], s2b[Ee];
    __shared__ float sg2[Ee], sb2[Ee], slw[Ee], slb;
    for (int i = threadIdx.x; i < Ee*Ee; i += blockDim.x) swo[i] = wo[i];
    for (int i = threadIdx.x; i < FFf*Ee; i += blockDim.x) { s1[i] = f1w[i]; s2[i] = f2w[i]; }
    if (threadIdx.x < FFf) s1b[threadIdx.x] = f1b[threadIdx.x];
    if (threadIdx.x < Ee) {
        sbo[threadIdx.x] = bo[threadIdx.x];
        sg1[threadIdx.x] = g1[threadIdx.x];
        sb1[threadIdx.x] = b1[threadIdx.x];
        s2b[threadIdx.x] = f2b[threadIdx.x];
        sg2[threadIdx.x] = g2[threadIdx.x];
        sb2[threadIdx.x] = b2[threadIdx.x];
        slw[threadIdx.x] = lw[threadIdx.x];
    }
    if (threadIdx.x == 0) slb = lb[0];
    __syncthreads();

    int row = blockIdx.x*blockDim.x + threadIdx.x;   // l-major: row = l*Ss + s
    if (row >= ROWS) return;
    int l = row / Ss, s = row % Ss;

    // gather ctx from the 4 heads
    float cx[Ee];
    #pragma unroll
    for (int h = 0; h < NHh; h++) {
        float4 o = g_ctx[(l*NHh + h)*Ss + s];
        cx[h*3] = o.x; cx[h*3+1] = o.y; cx[h*3+2] = o.z;
    }

    // recompute residual r = ce + pe + x
    int bi = s / (Cc*9);
    int rem = s % (Cc*9);
    int c = rem / 9, p = rem % 9;
    int pi = p/3, pj = p%3;
    int oi = l/WOo, oj = l%WOo;
    float xv = x[((bi*Cc + c)*Hh + pi + oi)*Ww + pj + oj];

    // out_proj + residual + LN1
    float t[Ee]; float mu = 0.f;
    #pragma unroll
    for (int e = 0; e < Ee; e++) {
        float acc = sbo[e];
        #pragma unroll
        for (int f = 0; f < Ee; f++) acc += cx[f] * swo[e*Ee + f];
        t[e] = (cemb[c*Ee + e] + pemb[l*Ee + e] + xv) + acc;
        mu += t[e];
    }
    mu *= (1.f/Ee);
    float var = 0.f;
    #pragma unroll
    for (int e = 0; e < Ee; e++) { float d = t[e]-mu; var += d*d; }
    var *= (1.f/Ee);
    float rs = rsqrtf(var + 1e-5f);

    float h1[Ee];
    #pragma unroll
    for (int e = 0; e < Ee; e++) h1[e] = (t[e]-mu)*rs*sg1[e] + sb1[e];

    float hid[FFf];
    #pragma unroll
    for (int f = 0; f < FFf; f++) {
        float acc = s1b[f];
        #pragma unroll
        for (int e = 0; e < Ee; e++) acc += h1[e] * s1[f*Ee + e];
        hid[f] = fmaxf(acc, 0.f);
    }

    float mu2 = 0.f;
    #pragma unroll
    for (int e = 0; e < Ee; e++) {
        float acc = s2b[e];
        #pragma unroll
        for (int f = 0; f < FFf; f++) acc += hid[f] * s2[e*FFf + f];
        t[e] = h1[e] + acc;
        mu2 += t[e];
    }
    mu2 *= (1.f/Ee);
    float var2 = 0.f;
    #pragma unroll
    for (int e = 0; e < Ee; e++) { float d = t[e]-mu2; var2 += d*d; }
    var2 *= (1.f/Ee);
    float rs2 = rsqrtf(var2 + 1e-5f);

    float proj = slb;
    #pragma unroll
    for (int e = 0; e < Ee; e++)
        proj += ((t[e]-mu2)*rs2*sg2[e] + sb2[e]) * slw[e];

    atomicAdd(&y[((bi*Cc + c)*Hh + (pi+oi))*Ww + (pj+oj)], proj);
}

// ---------------- launch ----------------
extern "C" void kernel_launch(void* const* d_in, const int* in_sizes, int n_in,
                              void* d_out, int out_size)
{
    const float* x    = (const float*)d_in[0];
    const float* ce   = (const float*)d_in[1];
    const float* pe   = (const float*)d_in[2];
    const float* ipw  = (const float*)d_in[3];
    const float* ipb  = (const float*)d_in[4];
    const float* opw  = (const float*)d_in[5];
    const float* opb  = (const float*)d_in[6];
    const float* ln1w = (const float*)d_in[7];
    const float* ln1b = (const float*)d_in[8];
    const float* f1w  = (const float*)d_in[9];
    const float* f1b  = (const float*)d_in[10];
    const float* f2w  = (const float*)d_in[11];
    const float* f2b  = (const float*)d_in[12];
    const float* ln2w = (const float*)d_in[13];
    const float* ln2b = (const float*)d_in[14];
    const float* lw   = (const float*)d_in[15];
    const float* lb   = (const float*)d_in[16];
    float* y = (float*)d_out;

    k_moments<<<5, 128>>>(x, y);
    k_tables<<<(NC*Cc + 127)/128, 128>>>(ce, pe, ipw, ipb);
    dim3 agrid(NC, Ss/128);
    k_attn2<<<agrid, 128>>>(x);
    k_post<<<ROWS/128, 128>>>(x, ce, pe, opw, opb, ln1w, ln1b,
                              f1w, f1b, f2w, f2b, ln2w, ln2b, lw, lb, y);
}

// round 9
// speedup vs baseline: 3.1811x; 1.1153x over previous
#include <cuda_runtime.h>
#include <math.h>

typedef unsigned long long ull;

// ---------------- problem constants ----------------
#define Bb   4
#define Cc   64
#define Hh   5
#define Ww   5
#define Kk   3
#define Ee   12
#define NHh  4
#define DHh  3
#define FFf  24
#define HOo  3
#define WOo  3
#define Ll   9
#define Ss   (Bb*Cc*Kk*Kk)       // 2304
#define ROWS (Ss*Ll)             // 20736
#define NC   (Ll*NHh)            // 36
#define YSZ  (Bb*Cc*Hh*Ww)       // 6400

#define DEG  14                  // Taylor degree: pairs j=0..14, moments M_0..M_15

// ---------------- scratch ----------------
__device__ float  TMg[Ll*Cc*32];        // per (l,c'): pairs {M_j/j!, M_{j+1}/j!} j=0..14 + pad (128B stride)
__device__ float4 TAg[NC*Cc];           // per (combo,c): {a0,a1,a2, gamma}   (a scaled 1/sqrt3)
__device__ float4 TBg[NC*Cc*2];         // per (combo,c'): {b*log2e, 0}, {v0, 0}
__device__ float4 TWg[NC];              // per combo: {delta, wv0, wv1, wv2}
__device__ float4 TUg[NHh];             // per head:  {u0,u1,u2,0}  (scaled 1/sqrt3)
__device__ float4 g_ctx[NC*Ss];         // attention output per (combo, s)

// ---------------- packed f32x2 helpers ----------------
__device__ __forceinline__ ull ffma2(ull a, ull b, ull c) {
    ull d; asm("fma.rn.f32x2 %0, %1, %2, %3;" : "=l"(d) : "l"(a), "l"(b), "l"(c)); return d;
}
__device__ __forceinline__ ull pack2(float lo, float hi) {
    ull d; asm("mov.b64 %0, {%1, %2};" : "=l"(d) : "f"(lo), "f"(hi)); return d;
}
__device__ __forceinline__ void unpack2(ull v, float& lo, float& hi) {
    asm("mov.b64 {%0, %1}, %2;" : "=f"(lo), "=f"(hi) : "l"(v));
}
__device__ __forceinline__ float ex2(float x) {
    float r; asm("ex2.approx.f32 %0, %1;" : "=f"(r) : "f"(x)); return r;
}

// ---------------- kernel 0: prep = moments (fp64) + affine tables + zero y ----------------
// gid in [0,576): moments thread per (l,c'). gid in [576, 2880): tables thread per (combo,c).
#define PREP_THREADS 2944
__global__ void k_prep(const float* __restrict__ x,
                       const float* __restrict__ ce,
                       const float* __restrict__ pe,
                       const float* __restrict__ ipw,
                       const float* __restrict__ ipb,
                       float* __restrict__ y)
{
    int gid = blockIdx.x*blockDim.x + threadIdx.x;
    for (int i = gid; i < YSZ; i += PREP_THREADS) y[i] = 0.f;

    if (gid < Ll*Cc) {
        // ---- moments ----
        int l = gid / Cc, c = gid % Cc;
        int oi = l / WOo, oj = l % WOo;

        double m[16];
        #pragma unroll
        for (int k = 0; k < 16; k++) m[k] = 0.0;

        for (int b = 0; b < Bb; b++) {
            #pragma unroll
            for (int p = 0; p < 9; p++) {
                int pi = p/3, pj = p%3;
                double xv = (double)x[((b*Cc + c)*Hh + pi + oi)*Ww + pj + oj];
                double pw = 1.0;
                #pragma unroll
                for (int k = 0; k < 16; k++) { m[k] += pw; pw *= xv; }
            }
        }

        float* dst = TMg + gid*32;
        double invf = 1.0;
        #pragma unroll
        for (int j = 0; j <= DEG; j++) {
            if (j > 0) invf /= (double)j;      // 1/j!
            dst[2*j]   = (float)(m[j]   * invf);
            dst[2*j+1] = (float)(m[j+1] * invf);
        }
        dst[30] = 0.f; dst[31] = 0.f;
    } else if (gid < Ll*Cc + NC*Cc) {
        // ---- tables ----
        int t = gid - Ll*Cc;
        int combo = t >> 6, c = t & 63;
        int l = combo >> 2, h = combo & 3;

        const float IS3 = 0.57735026918962576f;   // 1/sqrt(3)
        const float L2E = 1.4426950408889634f;

        float rc[Ee];
        #pragma unroll
        for (int f = 0; f < Ee; f++) rc[f] = ce[c*Ee + f] + pe[l*Ee + f];

        float a[3], b[3], v0[3], u[3], w[3], wv[3];
        #pragma unroll
        for (int d = 0; d < 3; d++) {
            const float* Wq = ipw + (3*h + d)*Ee;
            const float* Wk = ipw + (Ee + 3*h + d)*Ee;
            const float* Wv = ipw + (2*Ee + 3*h + d)*Ee;
            float aq = ipb[3*h + d];
            float ak = ipb[Ee + 3*h + d];
            float av = ipb[2*Ee + 3*h + d];
            float uq = 0.f, uk = 0.f, uv = 0.f;
            #pragma unroll
            for (int f = 0; f < Ee; f++) {
                float wq = Wq[f], wk = Wk[f], wvv = Wv[f];
                aq += wq*rc[f]; ak += wk*rc[f]; av += wvv*rc[f];
                uq += wq; uk += wk; uv += wvv;
            }
            a[d] = aq*IS3; b[d] = ak; v0[d] = av;
            u[d] = uq*IS3; w[d] = uk; wv[d] = uv;
        }
        float gamma = a[0]*w[0] + a[1]*w[1] + a[2]*w[2];
        float delta = u[0]*w[0] + u[1]*w[1] + u[2]*w[2];

        TAg[combo*Cc + c] = make_float4(a[0], a[1], a[2], gamma);
        TBg[(combo*Cc + c)*2 + 0] = make_float4(b[0]*L2E, b[1]*L2E, b[2]*L2E, 0.f);
        TBg[(combo*Cc + c)*2 + 1] = make_float4(v0[0], v0[1], v0[2], 0.f);
        if (c == 0) TWg[combo] = make_float4(delta, wv[0], wv[1], wv[2]);
        if (c == 0 && l == 0) TUg[h] = make_float4(u[0], u[1], u[2], 0.f);
    }
}

// ---------------- kernel 1: attention via channel moments ----------------
// grid (36 combos, 18 q-chunks), 128 threads, 1 query/thread.
// weight(s,t) = exp(q~·b_c' + g·x_t), g = q~·w. Sums over a channel's 36 tokens
// collapse to a Taylor dot against moments: S0=Σe^{gx}, S1=Σx·e^{gx}.
__global__ void k_attn(const float* __restrict__ x)
{
    __shared__ float4 sTB[Cc*2];            // {b~, v0} per c'
    __shared__ ulonglong2 sTM[Cc*8];        // 15 coeff pairs + pad per c' (128B)

    int combo = blockIdx.x;
    int l = combo >> 2, h = combo & 3;
    int tid = threadIdx.x;

    for (int i = tid; i < Cc*2; i += 128) sTB[i] = TBg[combo*Cc*2 + i];
    const ulonglong2* tms = (const ulonglong2*)(TMg + l*Cc*32);
    for (int i = tid; i < Cc*8; i += 128) sTM[i] = tms[i];
    __syncthreads();

    int s = blockIdx.y*128 + tid;
    int bi = s / (Cc*9);
    int rem = s % (Cc*9);
    int c = rem / 9, p = rem % 9;
    int pi = p/3, pj = p%3;
    int oi = l/WOo, oj = l%WOo;
    float xv = x[((bi*Cc + c)*Hh + pi + oi)*Ww + pj + oj];

    float4 ag = TAg[combo*Cc + c];
    float4 uu = TUg[h];
    float4 dw = TWg[combo];

    float q0 = ag.x + xv*uu.x;
    float q1 = ag.y + xv*uu.y;
    float q2 = ag.z + xv*uu.z;
    float g  = ag.w + xv*dw.x;              // q~·w
    ull  g2  = pack2(g, g);

    float den = 0.f, o0 = 0.f, o1 = 0.f, o2 = 0.f;

    #pragma unroll 2
    for (int cp = 0; cp < Cc; cp++) {
        float4 bb = sTB[cp*2];
        float4 vv = sTB[cp*2 + 1];
        const ull* Cp = (const ull*)&sTM[cp*8];

        float earg = fmaf(q0, bb.x, fmaf(q1, bb.y, q2*bb.z));   // already *log2e
        float E = ex2(earg);

        ull acc = Cp[DEG];
        #pragma unroll
        for (int j = DEG-1; j >= 0; j--) acc = ffma2(acc, g2, Cp[j]);
        float S0, S1; unpack2(acc, S0, S1);

        float ES0 = E*S0, ES1 = E*S1;
        den += ES0;
        o0 = fmaf(ES1, dw.y, fmaf(ES0, vv.x, o0));
        o1 = fmaf(ES1, dw.z, fmaf(ES0, vv.y, o1));
        o2 = fmaf(ES1, dw.w, fmaf(ES0, vv.z, o2));
    }

    float inv = 1.f / den;
    g_ctx[combo*Ss + s] = make_float4(o0*inv, o1*inv, o2*inv, 0.f);
}

// ---------------- kernel 2: out_proj + LN1 + FFN + LN2 + linear + fold ----------------
// TWO threads per row (lane pair): features split 6/6, LN/dots via shfl.
__global__ void k_post(const float* __restrict__ x,
                       const float* __restrict__ cemb, const float* __restrict__ pemb,
                       const float* __restrict__ wo, const float* __restrict__ bo,
                       const float* __restrict__ g1, const float* __restrict__ b1,
                       const float* __restrict__ f1w, const float* __restrict__ f1b,
                       const float* __restrict__ f2w, const float* __restrict__ f2b,
                       const float* __restrict__ g2, const float* __restrict__ b2,
                       const float* __restrict__ lw, const float* __restrict__ lb,
                       float* __restrict__ y)
{
    __shared__ float swo[Ee*Ee], sbo[Ee], sg1[Ee], sb1[Ee];
    __shared__ float s1[FFf*Ee], s1b[FFf], s2[Ee*FFf], s2b[Ee];
    __shared__ float sg2[Ee], sb2[Ee], slw[Ee], slb;
    __shared__ float sce[Cc*Ee], spe[Ll*Ee];
    for (int i = threadIdx.x; i < Ee*Ee; i += blockDim.x) swo[i] = wo[i];
    for (int i = threadIdx.x; i < FFf*Ee; i += blockDim.x) { s1[i] = f1w[i]; s2[i] = f2w[i]; }
    for (int i = threadIdx.x; i < Cc*Ee; i += blockDim.x) sce[i] = cemb[i];
    for (int i = threadIdx.x; i < Ll*Ee; i += blockDim.x) spe[i] = pemb[i];
    if (threadIdx.x < FFf) s1b[threadIdx.x] = f1b[threadIdx.x];
    if (threadIdx.x < Ee) {
        sbo[threadIdx.x] = bo[threadIdx.x];
        sg1[threadIdx.x] = g1[threadIdx.x];
        sb1[threadIdx.x] = b1[threadIdx.x];
        s2b[threadIdx.x] = f2b[threadIdx.x];
        sg2[threadIdx.x] = g2[threadIdx.x];
        sb2[threadIdx.x] = b2[threadIdx.x];
        slw[threadIdx.x] = lw[threadIdx.x];
    }
    if (threadIdx.x == 0) slb = lb[0];
    __syncthreads();

    int gt   = blockIdx.x*blockDim.x + threadIdx.x;
    int row  = gt >> 1;                  // l-major: row = l*Ss + s
    int half = gt & 1;
    int l = row / Ss, s = row % Ss;
    const unsigned FULL = 0xFFFFFFFFu;

    // gather ctx from the 4 heads (already normalized)
    float cx[Ee];
    #pragma unroll
    for (int h = 0; h < NHh; h++) {
        float4 o = g_ctx[(l*NHh + h)*Ss + s];
        cx[h*3] = o.x; cx[h*3+1] = o.y; cx[h*3+2] = o.z;
    }

    // recompute residual pieces
    int bi = s / (Cc*9);
    int rem = s % (Cc*9);
    int c = rem / 9, p = rem % 9;
    int pi = p/3, pj = p%3;
    int oi = l/WOo, oj = l%WOo;
    float xv = x[((bi*Cc + c)*Hh + pi + oi)*Ww + pj + oj];

    int ebase = half*6;

    // ---- out_proj + residual (own 6 outputs) ----
    float t[6];
    #pragma unroll
    for (int eo = 0; eo < 6; eo++) {
        int e = ebase + eo;
        float acc = sbo[e];
        #pragma unroll
        for (int f = 0; f < Ee; f++) acc += cx[f] * swo[e*Ee + f];
        t[eo] = (sce[c*Ee + e] + spe[l*Ee + e] + xv) + acc;
    }

    // ---- LN1 (pair reduction) ----
    float sl = 0.f;
    #pragma unroll
    for (int eo = 0; eo < 6; eo++) sl += t[eo];
    float mu = (sl + __shfl_xor_sync(FULL, sl, 1)) * (1.f/Ee);
    float vl = 0.f;
    #pragma unroll
    for (int eo = 0; eo < 6; eo++) { float d = t[eo]-mu; vl += d*d; }
    float var = (vl + __shfl_xor_sync(FULL, vl, 1)) * (1.f/Ee);
    float rs = rsqrtf(var + 1e-5f);

    float h1[6];
    #pragma unroll
    for (int eo = 0; eo < 6; eo++) {
        int e = ebase + eo;
        h1[eo] = (t[eo]-mu)*rs*sg1[e] + sb1[e];
    }

    // ---- FF1 (partial dot 6 + pair shfl) ----
    float hid[FFf];
    #pragma unroll
    for (int f = 0; f < FFf; f++) {
        float pd = 0.f;
        #pragma unroll
        for (int eo = 0; eo < 6; eo++) pd += h1[eo] * s1[f*Ee + ebase + eo];
        pd += __shfl_xor_sync(FULL, pd, 1);
        hid[f] = fmaxf(pd + s1b[f], 0.f);
    }

    // ---- FF2 + residual (own 6 outputs) ----
    float t2[6];
    #pragma unroll
    for (int eo = 0; eo < 6; eo++) {
        int e = ebase + eo;
        float acc = s2b[e];
        #pragma unroll
        for (int f = 0; f < FFf; f++) acc += hid[f] * s2[e*FFf + f];
        t2[eo] = h1[eo] + acc;
    }

    // ---- LN2 (pair reduction) ----
    float sl2 = 0.f;
    #pragma unroll
    for (int eo = 0; eo < 6; eo++) sl2 += t2[eo];
    float mu2 = (sl2 + __shfl_xor_sync(FULL, sl2, 1)) * (1.f/Ee);
    float vl2 = 0.f;
    #pragma unroll
    for (int eo = 0; eo < 6; eo++) { float d = t2[eo]-mu2; vl2 += d*d; }
    float var2 = (vl2 + __shfl_xor_sync(FULL, vl2, 1)) * (1.f/Ee);
    float rs2 = rsqrtf(var2 + 1e-5f);

    // ---- final linear (pair-reduced dot) ----
    float pl = 0.f;
    #pragma unroll
    for (int eo = 0; eo < 6; eo++) {
        int e = ebase + eo;
        pl += ((t2[eo]-mu2)*rs2*sg2[e] + sb2[e]) * slw[e];
    }
    pl += __shfl_xor_sync(FULL, pl, 1);

    if (half == 0) {
        float proj = slb + pl;
        atomicAdd(&y[((bi*Cc + c)*Hh + (pi+oi))*Ww + (pj+oj)], proj);
    }
}

// ---------------- launch ----------------
extern "C" void kernel_launch(void* const* d_in, const int* in_sizes, int n_in,
                              void* d_out, int out_size)
{
    const float* x    = (const float*)d_in[0];
    const float* ce   = (const float*)d_in[1];
    const float* pe   = (const float*)d_in[2];
    const float* ipw  = (const float*)d_in[3];
    const float* ipb  = (const float*)d_in[4];
    const float* opw  = (const float*)d_in[5];
    const float* opb  = (const float*)d_in[6];
    const float* ln1w = (const float*)d_in[7];
    const float* ln1b = (const float*)d_in[8];
    const float* f1w  = (const float*)d_in[9];
    const float* f1b  = (const float*)d_in[10];
    const float* f2w  = (const float*)d_in[11];
    const float* f2b  = (const float*)d_in[12];
    const float* ln2w = (const float*)d_in[13];
    const float* ln2b = (const float*)d_in[14];
    const float* lw   = (const float*)d_in[15];
    const float* lb   = (const float*)d_in[16];
    float* y = (float*)d_out;

    k_prep<<<PREP_THREADS/128, 128>>>(x, ce, pe, ipw, ipb, y);
    dim3 agrid(NC, Ss/128);
    k_attn<<<agrid, 128>>>(x);
    k_post<<<ROWS*2/128, 128>>>(x, ce, pe, opw, opb, ln1w, ln1b,
                                f1w, f1b, f2w, f2b, ln2w, ln2b, lw, lb, y);
}

// round 10
// speedup vs baseline: 3.4760x; 1.0927x over previous
#include <cuda_runtime.h>
#include <math.h>

typedef unsigned long long ull;

// ---------------- problem constants ----------------
#define Bb   4
#define Cc   64
#define Hh   5
#define Ww   5
#define Kk   3
#define Ee   12
#define NHh  4
#define DHh  3
#define FFf  24
#define HOo  3
#define WOo  3
#define Ll   9
#define Ss   (Bb*Cc*Kk*Kk)       // 2304
#define ROWS (Ss*Ll)             // 20736
#define NC   (Ll*NHh)            // 36
#define YSZ  (Bb*Cc*Hh*Ww)       // 6400

#define DEG  14                  // Taylor degree: pairs j=0..14, moments M_0..M_15

// ---------------- scratch ----------------
__device__ float4 g_ctx[NC*Ss];         // attention output per (combo, s)

// ---------------- packed f32x2 helpers ----------------
__device__ __forceinline__ ull ffma2(ull a, ull b, ull c) {
    ull d; asm("fma.rn.f32x2 %0, %1, %2, %3;" : "=l"(d) : "l"(a), "l"(b), "l"(c)); return d;
}
__device__ __forceinline__ ull pack2(float lo, float hi) {
    ull d; asm("mov.b64 %0, {%1, %2};" : "=l"(d) : "f"(lo), "f"(hi)); return d;
}
__device__ __forceinline__ void unpack2(ull v, float& lo, float& hi) {
    asm("mov.b64 {%0, %1}, %2;" : "=f"(lo), "=f"(hi) : "l"(v));
}
__device__ __forceinline__ float ex2(float x) {
    float r; asm("ex2.approx.f32 %0, %1;" : "=f"(r) : "f"(x)); return r;
}

// ---------------- kernel 1: attention (fused moments + tables + Taylor softmax) ----------------
// grid (36 combos, 18 q-chunks), 128 threads, 1 query/thread.
// Prologue per block: fp32 channel moments for l (2 thr/channel) + affine tables for combo.
// weight(s,t) = exp(q~·b_c' + g·x_t), g = q~·w; channel sums collapse to Taylor dots vs moments.
__global__ void k_attn(const float* __restrict__ x,
                       const float* __restrict__ ce,
                       const float* __restrict__ pe,
                       const float* __restrict__ ipw,
                       const float* __restrict__ ipb,
                       float* __restrict__ y)
{
    __shared__ ulonglong2 sTM[Cc*8];        // per c': 15 pairs {M_j/j!, M_{j+1}/j!} + pad (128B)
    __shared__ float4 sTB[Cc*2];            // per c': {b*log2e, 0}, {v0, 0}
    __shared__ float4 sTA[Cc];              // per c (query side): {a0,a1,a2, gamma}
    __shared__ float  sUW[8];               // {u0,u1,u2, delta, wv0,wv1,wv2, -}

    int combo = blockIdx.x;
    int l = combo >> 2, h = combo & 3;
    int tid = threadIdx.x;
    int oi = l/WOo, oj = l%WOo;
    const unsigned FULL = 0xFFFFFFFFu;

    // zero output once (combo 0 blocks; completes before k_post launch)
    if (combo == 0) {
        for (int i = blockIdx.y*128 + tid; i < YSZ; i += 18*128) y[i] = 0.f;
    }

    // ---- moments: 2 threads per channel, 18 samples each ----
    {
        int ch = tid >> 1, hf = tid & 1;
        float m[16];
        #pragma unroll
        for (int k = 0; k < 16; k++) m[k] = 0.f;

        #pragma unroll
        for (int bb = 0; bb < 2; bb++) {
            int b = hf*2 + bb;
            #pragma unroll
            for (int p = 0; p < 9; p++) {
                float xv = x[((b*Cc + ch)*Hh + (p/3) + oi)*Ww + (p%3) + oj];
                float pw = 1.f;
                #pragma unroll
                for (int k = 0; k < 16; k++) { m[k] += pw; pw *= xv; }
            }
        }
        #pragma unroll
        for (int k = 0; k < 16; k++) m[k] += __shfl_xor_sync(FULL, m[k], 1);

        if (hf == 0) {
            float* dst = (float*)&sTM[ch*8];
            float invf = 1.f;
            #pragma unroll
            for (int j = 0; j <= DEG; j++) {
                if (j > 0) invf /= (float)j;      // 1/j!
                dst[2*j]   = m[j]   * invf;
                dst[2*j+1] = m[j+1] * invf;
            }
            dst[30] = 0.f; dst[31] = 0.f;
        }
    }

    // ---- tables: thread per channel (tid < 64) ----
    const float IS3 = 0.57735026918962576f;
    const float L2E = 1.4426950408889634f;
    if (tid < Cc) {
        int c = tid;
        float rc[Ee];
        #pragma unroll
        for (int f = 0; f < Ee; f++) rc[f] = ce[c*Ee + f] + pe[l*Ee + f];

        float a[3], b[3], v0[3], w[3];
        #pragma unroll
        for (int d = 0; d < 3; d++) {
            const float* Wq = ipw + (3*h + d)*Ee;
            const float* Wk = ipw + (Ee + 3*h + d)*Ee;
            const float* Wv = ipw + (2*Ee + 3*h + d)*Ee;
            float aq = ipb[3*h + d];
            float ak = ipb[Ee + 3*h + d];
            float av = ipb[2*Ee + 3*h + d];
            float uk = 0.f;
            #pragma unroll
            for (int f = 0; f < Ee; f++) {
                aq += Wq[f]*rc[f]; ak += Wk[f]*rc[f]; av += Wv[f]*rc[f];
                uk += Wk[f];
            }
            a[d] = aq*IS3; b[d] = ak; v0[d] = av; w[d] = uk;
        }
        float gamma = a[0]*w[0] + a[1]*w[1] + a[2]*w[2];
        sTA[c] = make_float4(a[0], a[1], a[2], gamma);
        sTB[c*2 + 0] = make_float4(b[0]*L2E, b[1]*L2E, b[2]*L2E, 0.f);
        sTB[c*2 + 1] = make_float4(v0[0], v0[1], v0[2], 0.f);
    } else if (tid == 64) {
        // per-combo: u (q row-sums, scaled), w (k row-sums), wv (v row-sums), delta=u·w
        float u[3], w[3], wv[3];
        #pragma unroll
        for (int d = 0; d < 3; d++) {
            float uq = 0.f, uk = 0.f, uv = 0.f;
            #pragma unroll
            for (int f = 0; f < Ee; f++) {
                uq += ipw[(3*h + d)*Ee + f];
                uk += ipw[(Ee + 3*h + d)*Ee + f];
                uv += ipw[(2*Ee + 3*h + d)*Ee + f];
            }
            u[d] = uq*IS3; w[d] = uk; wv[d] = uv;
        }
        sUW[0] = u[0]; sUW[1] = u[1]; sUW[2] = u[2];
        sUW[3] = u[0]*w[0] + u[1]*w[1] + u[2]*w[2];   // delta
        sUW[4] = wv[0]; sUW[5] = wv[1]; sUW[6] = wv[2];
    }
    __syncthreads();

    // ---- per-query main loop ----
    int s = blockIdx.y*128 + tid;
    int bi = s / (Cc*9);
    int rem = s % (Cc*9);
    int c = rem / 9, p = rem % 9;
    float xv = x[((bi*Cc + c)*Hh + (p/3) + oi)*Ww + (p%3) + oj];

    float4 ag = sTA[c];
    float u0 = sUW[0], u1 = sUW[1], u2 = sUW[2], delta = sUW[3];
    float wv0 = sUW[4], wv1 = sUW[5], wv2 = sUW[6];

    float q0 = ag.x + xv*u0;
    float q1 = ag.y + xv*u1;
    float q2 = ag.z + xv*u2;
    float g  = ag.w + xv*delta;             // q~·w
    ull  g2  = pack2(g, g);

    float den = 0.f, o0 = 0.f, o1 = 0.f, o2 = 0.f;

    #pragma unroll 2
    for (int cp = 0; cp < Cc; cp++) {
        float4 bb = sTB[cp*2];
        float4 vv = sTB[cp*2 + 1];
        const ull* Cp = (const ull*)&sTM[cp*8];

        float earg = fmaf(q0, bb.x, fmaf(q1, bb.y, q2*bb.z));   // already *log2e
        float E = ex2(earg);

        ull acc = Cp[DEG];
        #pragma unroll
        for (int j = DEG-1; j >= 0; j--) acc = ffma2(acc, g2, Cp[j]);
        float S0, S1; unpack2(acc, S0, S1);

        float ES0 = E*S0, ES1 = E*S1;
        den += ES0;
        o0 = fmaf(ES1, wv0, fmaf(ES0, vv.x, o0));
        o1 = fmaf(ES1, wv1, fmaf(ES0, vv.y, o1));
        o2 = fmaf(ES1, wv2, fmaf(ES0, vv.z, o2));
    }

    float inv = 1.f / den;
    g_ctx[combo*Ss + s] = make_float4(o0*inv, o1*inv, o2*inv, 0.f);
}

// ---------------- kernel 2: out_proj + LN1 + FFN + LN2 + linear + fold ----------------
// TWO threads per row (lane pair): features split 6/6, LN/dots via shfl.
__global__ void k_post(const float* __restrict__ x,
                       const float* __restrict__ cemb, const float* __restrict__ pemb,
                       const float* __restrict__ wo, const float* __restrict__ bo,
                       const float* __restrict__ g1, const float* __restrict__ b1,
                       const float* __restrict__ f1w, const float* __restrict__ f1b,
                       const float* __restrict__ f2w, const float* __restrict__ f2b,
                       const float* __restrict__ g2, const float* __restrict__ b2,
                       const float* __restrict__ lw, const float* __restrict__ lb,
                       float* __restrict__ y)
{
    __shared__ float swo[Ee*Ee], sbo[Ee], sg1[Ee], sb1[Ee];
    __shared__ float s1[FFf*Ee], s1b[FFf], s2[Ee*FFf], s2b[Ee];
    __shared__ float sg2[Ee], sb2[Ee], slw[Ee], slb;
    __shared__ float sce[Cc*Ee], spe[Ll*Ee];
    for (int i = threadIdx.x; i < Ee*Ee; i += blockDim.x) swo[i] = wo[i];
    for (int i = threadIdx.x; i < FFf*Ee; i += blockDim.x) { s1[i] = f1w[i]; s2[i] = f2w[i]; }
    for (int i = threadIdx.x; i < Cc*Ee; i += blockDim.x) sce[i] = cemb[i];
    for (int i = threadIdx.x; i < Ll*Ee; i += blockDim.x) spe[i] = pemb[i];
    if (threadIdx.x < FFf) s1b[threadIdx.x] = f1b[threadIdx.x];
    if (threadIdx.x < Ee) {
        sbo[threadIdx.x] = bo[threadIdx.x];
        sg1[threadIdx.x] = g1[threadIdx.x];
        sb1[threadIdx.x] = b1[threadIdx.x];
        s2b[threadIdx.x] = f2b[threadIdx.x];
        sg2[threadIdx.x] = g2[threadIdx.x];
        sb2[threadIdx.x] = b2[threadIdx.x];
        slw[threadIdx.x] = lw[threadIdx.x];
    }
    if (threadIdx.x == 0) slb = lb[0];
    __syncthreads();

    int gt   = blockIdx.x*blockDim.x + threadIdx.x;
    int row  = gt >> 1;                  // l-major: row = l*Ss + s
    int half = gt & 1;
    int l = row / Ss, s = row % Ss;
    const unsigned FULL = 0xFFFFFFFFu;

    // gather ctx from the 4 heads (already normalized)
    float cx[Ee];
    #pragma unroll
    for (int h = 0; h < NHh; h++) {
        float4 o = g_ctx[(l*NHh + h)*Ss + s];
        cx[h*3] = o.x; cx[h*3+1] = o.y; cx[h*3+2] = o.z;
    }

    int bi = s / (Cc*9);
    int rem = s % (Cc*9);
    int c = rem / 9, p = rem % 9;
    int pi = p/3, pj = p%3;
    int oi = l/WOo, oj = l%WOo;
    float xv = x[((bi*Cc + c)*Hh + pi + oi)*Ww + pj + oj];

    int ebase = half*6;

    // ---- out_proj + residual (own 6 outputs) ----
    float t[6];
    #pragma unroll
    for (int eo = 0; eo < 6; eo++) {
        int e = ebase + eo;
        float acc = sbo[e];
        #pragma unroll
        for (int f = 0; f < Ee; f++) acc += cx[f] * swo[e*Ee + f];
        t[eo] = (sce[c*Ee + e] + spe[l*Ee + e] + xv) + acc;
    }

    // ---- LN1 (pair reduction) ----
    float sl = 0.f;
    #pragma unroll
    for (int eo = 0; eo < 6; eo++) sl += t[eo];
    float mu = (sl + __shfl_xor_sync(FULL, sl, 1)) * (1.f/Ee);
    float vl = 0.f;
    #pragma unroll
    for (int eo = 0; eo < 6; eo++) { float d = t[eo]-mu; vl += d*d; }
    float var = (vl + __shfl_xor_sync(FULL, vl, 1)) * (1.f/Ee);
    float rs = rsqrtf(var + 1e-5f);

    float h1[6];
    #pragma unroll
    for (int eo = 0; eo < 6; eo++) {
        int e = ebase + eo;
        h1[eo] = (t[eo]-mu)*rs*sg1[e] + sb1[e];
    }

    // ---- FF1 (partial dot 6 + pair shfl) ----
    float hid[FFf];
    #pragma unroll
    for (int f = 0; f < FFf; f++) {
        float pd = 0.f;
        #pragma unroll
        for (int eo = 0; eo < 6; eo++) pd += h1[eo] * s1[f*Ee + ebase + eo];
        pd += __shfl_xor_sync(FULL, pd, 1);
        hid[f] = fmaxf(pd + s1b[f], 0.f);
    }

    // ---- FF2 + residual (own 6 outputs) ----
    float t2[6];
    #pragma unroll
    for (int eo = 0; eo < 6; eo++) {
        int e = ebase + eo;
        float acc = s2b[e];
        #pragma unroll
        for (int f = 0; f < FFf; f++) acc += hid[f] * s2[e*FFf + f];
        t2[eo] = h1[eo] + acc;
    }

    // ---- LN2 (pair reduction) ----
    float sl2 = 0.f;
    #pragma unroll
    for (int eo = 0; eo < 6; eo++) sl2 += t2[eo];
    float mu2 = (sl2 + __shfl_xor_sync(FULL, sl2, 1)) * (1.f/Ee);
    float vl2 = 0.f;
    #pragma unroll
    for (int eo = 0; eo < 6; eo++) { float d = t2[eo]-mu2; vl2 += d*d; }
    float var2 = (vl2 + __shfl_xor_sync(FULL, vl2, 1)) * (1.f/Ee);
    float rs2 = rsqrtf(var2 + 1e-5f);

    // ---- final linear (pair-reduced dot) ----
    float pl = 0.f;
    #pragma unroll
    for (int eo = 0; eo < 6; eo++) {
        int e = ebase + eo;
        pl += ((t2[eo]-mu2)*rs2*sg2[e] + sb2[e]) * slw[e];
    }
    pl += __shfl_xor_sync(FULL, pl, 1);

    if (half == 0) {
        float proj = slb + pl;
        atomicAdd(&y[((bi*Cc + c)*Hh + (pi+oi))*Ww + (pj+oj)], proj);
    }
}

// ---------------- launch ----------------
extern "C" void kernel_launch(void* const* d_in, const int* in_sizes, int n_in,
                              void* d_out, int out_size)
{
    const float* x    = (const float*)d_in[0];
    const float* ce   = (const float*)d_in[1];
    const float* pe   = (const float*)d_in[2];
    const float* ipw  = (const float*)d_in[3];
    const float* ipb  = (const float*)d_in[4];
    const float* opw  = (const float*)d_in[5];
    const float* opb  = (const float*)d_in[6];
    const float* ln1w = (const float*)d_in[7];
    const float* ln1b = (const float*)d_in[8];
    const float* f1w  = (const float*)d_in[9];
    const float* f1b  = (const float*)d_in[10];
    const float* f2w  = (const float*)d_in[11];
    const float* f2b  = (const float*)d_in[12];
    const float* ln2w = (const float*)d_in[13];
    const float* ln2b = (const float*)d_in[14];
    const float* lw   = (const float*)d_in[15];
    const float* lb   = (const float*)d_in[16];
    float* y = (float*)d_out;

    dim3 agrid(NC, Ss/128);
    k_attn<<<agrid, 128>>>(x, ce, pe, ipw, ipb, y);
    k_post<<<ROWS*2/128, 128>>>(x, ce, pe, opw, opb, ln1w, ln1b,
                                f1w, f1b, f2w, f2b, ln2w, ln2b, lw, lb, y);
}